// round 1
// baseline (speedup 1.0000x reference)
#include <cuda_runtime.h>
#include <cstdint>

#define HEADS   16
#define DHEAD   64
#define BATCH   2
#define NSEQ    2048
#define DIM     1024
#define SCALE   0.125f   // 64^-0.5

// Scratch (allocation-free contract: __device__ globals)
__device__ float g_w[(size_t)BATCH * NSEQ * DIM];    // shared q=k=v projection, (b*n, h*64+d)
__device__ float g_att[(size_t)BATCH * NSEQ * DIM];  // attention output, same layout

// ---------------------------------------------------------------------------
// SGEMM: C[M,N] = A[M,K] @ B[K,N] (+ bias per column). 128x128 tile, BK=16,
// 256 threads, 8x8 microtile. A staged transposed in smem.
// ---------------------------------------------------------------------------
#define BM 128
#define BN 128
#define BK 16

__global__ __launch_bounds__(256) void sgemm_kernel(
    const float* __restrict__ A, const float* __restrict__ Bm,
    const float* __restrict__ bias, float* __restrict__ C,
    int M, int N, int K)
{
    __shared__ float As[BK][BM];   // As[k][m]
    __shared__ float Bs[BK][BN];   // Bs[k][n]

    const int tid = threadIdx.x;
    const int tx  = tid & 15;
    const int ty  = tid >> 4;
    const int m0  = blockIdx.y * BM;
    const int n0  = blockIdx.x * BN;

    float acc[8][8];
    #pragma unroll
    for (int r = 0; r < 8; r++)
        #pragma unroll
        for (int c = 0; c < 8; c++) acc[r][c] = 0.0f;

    for (int k0 = 0; k0 < K; k0 += BK) {
        // Stage A (transposed) and B. 512 float4 each; 2 per thread.
        #pragma unroll
        for (int i = 0; i < 2; i++) {
            int f = tid * 2 + i;
            // A: row = f>>2 (0..127), kq = (f&3)*4
            int arow = f >> 2;
            int kq   = (f & 3) * 4;
            float4 a = *(const float4*)&A[(size_t)(m0 + arow) * K + k0 + kq];
            As[kq + 0][arow] = a.x;
            As[kq + 1][arow] = a.y;
            As[kq + 2][arow] = a.z;
            As[kq + 3][arow] = a.w;
            // B: krow = f>>5 (0..15), c4 = (f&31)*4
            int krow = f >> 5;
            int c4   = (f & 31) * 4;
            *(float4*)&Bs[krow][c4] =
                *(const float4*)&Bm[(size_t)(k0 + krow) * N + n0 + c4];
        }
        __syncthreads();

        #pragma unroll
        for (int k = 0; k < BK; k++) {
            float a[8], b[8];
            *(float4*)&a[0] = *(const float4*)&As[k][ty * 8];
            *(float4*)&a[4] = *(const float4*)&As[k][ty * 8 + 4];
            *(float4*)&b[0] = *(const float4*)&Bs[k][tx * 8];
            *(float4*)&b[4] = *(const float4*)&Bs[k][tx * 8 + 4];
            #pragma unroll
            for (int r = 0; r < 8; r++)
                #pragma unroll
                for (int c = 0; c < 8; c++)
                    acc[r][c] += a[r] * b[c];
        }
        __syncthreads();
    }

    #pragma unroll
    for (int r = 0; r < 8; r++) {
        int row = m0 + ty * 8 + r;
        #pragma unroll
        for (int c = 0; c < 8; c += 4) {
            int col = n0 + tx * 8 + c;
            float4 v = make_float4(acc[r][c], acc[r][c + 1], acc[r][c + 2], acc[r][c + 3]);
            if (bias) {
                v.x += bias[col];     v.y += bias[col + 1];
                v.z += bias[col + 2]; v.w += bias[col + 3];
            }
            *(float4*)&C[(size_t)row * N + col] = v;
        }
    }
}

// ---------------------------------------------------------------------------
// Attention (q=k=v=w). One CTA = one (b,h) x 64-row Q block. Flash-style
// online softmax over unmasked scores; post-softmax column mask folded into
// the PV numerator only. 256 threads (16x16), 4x4 microtiles.
// ---------------------------------------------------------------------------
#define PITCH 68          // 64 + 4 pad (float4-aligned rows)
#define QBLK  64

__global__ __launch_bounds__(256) void attn_kernel(const int* __restrict__ mask)
{
    extern __shared__ float smem[];
    float* Qt = smem;                  // Qt[d][r]  (scaled)
    float* Kt = Qt + QBLK * PITCH;     // Kt[d][j]
    float* Ks = Kt + QBLK * PITCH;     // Ks[j][d]  == V
    float* Ps = Ks + QBLK * PITCH;     // Ps[r][j]  masked probs
    float* Ms = Ps + QBLK * PITCH;     // Ms[j] = 1 - mask

    const int tid = threadIdx.x;
    const int tx  = tid & 15;
    const int ty  = tid >> 4;
    const int qb  = blockIdx.x;
    const int h   = blockIdx.y;
    const int b   = blockIdx.z;
    const int i0  = qb * QBLK;

    const float* wbase = g_w + (size_t)b * NSEQ * DIM + h * DHEAD;
    const int*   mrow  = mask + (size_t)b * NSEQ;

    // Load Q tile, transposed + pre-scaled. j = tid%64 keeps scatter stores
    // conflict-free (32 lanes -> 32 distinct banks).
    {
        int r = tid & 63;
        int dbase = (tid >> 6) * 16;
        const float* src = wbase + (size_t)(i0 + r) * DIM + dbase;
        #pragma unroll
        for (int q = 0; q < 4; q++) {
            float4 v = *(const float4*)(src + q * 4);
            int d = dbase + q * 4;
            Qt[(d + 0) * PITCH + r] = v.x * SCALE;
            Qt[(d + 1) * PITCH + r] = v.y * SCALE;
            Qt[(d + 2) * PITCH + r] = v.z * SCALE;
            Qt[(d + 3) * PITCH + r] = v.w * SCALE;
        }
    }

    float mrun[4], lrun[4], O[4][4];
    #pragma unroll
    for (int rr = 0; rr < 4; rr++) {
        mrun[rr] = -1e30f;
        lrun[rr] = 0.0f;
        #pragma unroll
        for (int cc = 0; cc < 4; cc++) O[rr][cc] = 0.0f;
    }

    for (int j0 = 0; j0 < NSEQ; j0 += QBLK) {
        __syncthreads();   // previous PV done -> safe to overwrite Ks/Kt

        // Load K/V tile: row-major (V) + transposed (for S), plus mask slice.
        {
            int j = tid & 63;
            int dbase = (tid >> 6) * 16;
            const float* src = wbase + (size_t)(j0 + j) * DIM + dbase;
            #pragma unroll
            for (int q = 0; q < 4; q++) {
                float4 v = *(const float4*)(src + q * 4);
                int d = dbase + q * 4;
                *(float4*)&Ks[j * PITCH + d] = v;
                Kt[(d + 0) * PITCH + j] = v.x;
                Kt[(d + 1) * PITCH + j] = v.y;
                Kt[(d + 2) * PITCH + j] = v.z;
                Kt[(d + 3) * PITCH + j] = v.w;
            }
            if (tid < QBLK) Ms[tid] = 1.0f - (float)mrow[j0 + tid];
        }
        __syncthreads();

        // S = (Q*scale) @ K^T for this 64x64 tile, 4x4 per thread.
        float s[4][4];
        #pragma unroll
        for (int rr = 0; rr < 4; rr++)
            #pragma unroll
            for (int jj = 0; jj < 4; jj++) s[rr][jj] = 0.0f;

        #pragma unroll 8
        for (int d = 0; d < QBLK; d++) {
            float4 q4 = *(const float4*)&Qt[d * PITCH + ty * 4];
            float4 k4 = *(const float4*)&Kt[d * PITCH + tx * 4];
            float qa[4] = {q4.x, q4.y, q4.z, q4.w};
            float ka[4] = {k4.x, k4.y, k4.z, k4.w};
            #pragma unroll
            for (int rr = 0; rr < 4; rr++)
                #pragma unroll
                for (int jj = 0; jj < 4; jj++)
                    s[rr][jj] += qa[rr] * ka[jj];
        }

        // Online softmax update (UNMASKED max & sum, per reference).
        #pragma unroll
        for (int rr = 0; rr < 4; rr++) {
            float rmax = s[rr][0];
            rmax = fmaxf(rmax, s[rr][1]);
            rmax = fmaxf(rmax, s[rr][2]);
            rmax = fmaxf(rmax, s[rr][3]);
            #pragma unroll
            for (int off = 8; off > 0; off >>= 1)
                rmax = fmaxf(rmax, __shfl_xor_sync(0xffffffffu, rmax, off, 16));

            float mnew = fmaxf(mrun[rr], rmax);
            float corr = __expf(mrun[rr] - mnew);

            float p0 = __expf(s[rr][0] - mnew);
            float p1 = __expf(s[rr][1] - mnew);
            float p2 = __expf(s[rr][2] - mnew);
            float p3 = __expf(s[rr][3] - mnew);
            s[rr][0] = p0; s[rr][1] = p1; s[rr][2] = p2; s[rr][3] = p3;

            float rsum = p0 + p1 + p2 + p3;
            #pragma unroll
            for (int off = 8; off > 0; off >>= 1)
                rsum += __shfl_xor_sync(0xffffffffu, rsum, off, 16);

            lrun[rr] = lrun[rr] * corr + rsum;
            mrun[rr] = mnew;
            #pragma unroll
            for (int cc = 0; cc < 4; cc++) O[rr][cc] *= corr;
        }

        // Store masked P (mask applied to numerator only).
        {
            float4 mv = *(const float4*)&Ms[tx * 4];
            #pragma unroll
            for (int rr = 0; rr < 4; rr++) {
                float4 pv = make_float4(s[rr][0] * mv.x, s[rr][1] * mv.y,
                                        s[rr][2] * mv.z, s[rr][3] * mv.w);
                *(float4*)&Ps[(ty * 4 + rr) * PITCH + tx * 4] = pv;
            }
        }
        __syncthreads();

        // O += P @ V. P read via 16-lane broadcast, V via float4.
        #pragma unroll 4
        for (int j = 0; j < QBLK; j++) {
            float4 v = *(const float4*)&Ks[j * PITCH + tx * 4];
            #pragma unroll
            for (int rr = 0; rr < 4; rr++) {
                float p = Ps[(ty * 4 + rr) * PITCH + j];
                O[rr][0] += p * v.x;
                O[rr][1] += p * v.y;
                O[rr][2] += p * v.z;
                O[rr][3] += p * v.w;
            }
        }
    }

    // Normalize and store to g_att in (b, n, h*64+d) layout.
    float* obase = g_att + ((size_t)b * NSEQ + i0) * DIM + h * DHEAD;
    #pragma unroll
    for (int rr = 0; rr < 4; rr++) {
        float inv = 1.0f / lrun[rr];
        float4 o = make_float4(O[rr][0] * inv, O[rr][1] * inv,
                               O[rr][2] * inv, O[rr][3] * inv);
        *(float4*)&obase[(size_t)(ty * 4 + rr) * DIM + tx * 4] = o;
    }
}

// ---------------------------------------------------------------------------
// Launch: x @ Wqkv -> attention -> @ Wout + bout
// ---------------------------------------------------------------------------
extern "C" void kernel_launch(void* const* d_in, const int* in_sizes, int n_in,
                              void* d_out, int out_size)
{
    const float* x    = (const float*)d_in[0];
    const int*   mask = (const int*)d_in[1];
    const float* Wqkv = (const float*)d_in[2];
    const float* Wout = (const float*)d_in[3];
    const float* bout = (const float*)d_in[4];
    float*       out  = (float*)d_out;

    float *wp = nullptr, *ap = nullptr;
    cudaGetSymbolAddress((void**)&wp, g_w);
    cudaGetSymbolAddress((void**)&ap, g_att);

    const int M = BATCH * NSEQ;          // 4096
    dim3 gg(DIM / BN, M / BM);           // (8, 32)

    // Stage 1: w = x @ Wqkv
    sgemm_kernel<<<gg, 256>>>(x, Wqkv, nullptr, wp, M, DIM, DIM);

    // Stage 2: attention
    size_t smem_bytes = (size_t)(4 * QBLK * PITCH + QBLK) * sizeof(float);  // ~70 KB
    cudaFuncSetAttribute(attn_kernel, cudaFuncAttributeMaxDynamicSharedMemorySize,
                         (int)smem_bytes);
    dim3 ga(NSEQ / QBLK, HEADS, BATCH);  // (32, 16, 2)
    attn_kernel<<<ga, 256, smem_bytes>>>(mask);

    // Stage 3: out = att @ Wout + bout
    sgemm_kernel<<<gg, 256>>>(ap, Wout, bout, out, M, DIM, DIM);
}